// round 7
// baseline (speedup 1.0000x reference)
#include <cuda_runtime.h>
#include <cuda_fp16.h>
#include <cstdint>

// Lingunet5Filter — HMMA fp16 single-product GEMM:
//   D = fp16(F) * fp16(X), fp32 accum.  Aggregate rel err ~3e-4 (threshold 1e-3).
//   Y[b](128 x N) = F[b](128x128) @ X[b](128 x N), N in {16384,4096,1024,256,64}, B=32
// + register-resident instance-norm kernels (levels 0-3).

#define EPSN  1e-5f
#define PITCH 136   // fp16 elems per smem row (272 B) -> ldmatrix conflict-free
#define FPITCH 132  // float elems per epilogue bounce row

static __device__ __forceinline__ uint32_t smem_u32(const void* p) {
    uint32_t a;
    asm("{ .reg .u64 t; cvta.to.shared.u64 t, %1; cvt.u32.u64 %0, t; }" : "=r"(a) : "l"(p));
    return a;
}
static __device__ __forceinline__ uint32_t pack_h2(float a, float b) {
    __half2 t = __floats2half2_rn(a, b);
    return *reinterpret_cast<uint32_t*>(&t);
}

#define LDSM4(r, addr)                                                          \
    asm volatile("ldmatrix.sync.aligned.m8n8.x4.shared.b16 {%0,%1,%2,%3}, [%4];" \
                 : "=r"((r)[0]), "=r"((r)[1]), "=r"((r)[2]), "=r"((r)[3])        \
                 : "r"(addr))

#define MMA16816(d, a, b0, b1)                                                  \
    asm volatile("mma.sync.aligned.m16n8k16.row.col.f32.f16.f16.f32 "            \
                 "{%0,%1,%2,%3}, {%4,%5,%6,%7}, {%8,%9}, {%0,%1,%2,%3};"         \
                 : "+f"((d)[0]), "+f"((d)[1]), "+f"((d)[2]), "+f"((d)[3])        \
                 : "r"((a)[0]), "r"((a)[1]), "r"((a)[2]), "r"((a)[3]),           \
                   "r"(b0), "r"(b1))

// ---------------- kernel 1: HMMA batched GEMM (CTA tile 128m x 128n, K=128) ----------------
__global__ __launch_bounds__(256, 3)
void lg5_hmma(const float* __restrict__ x0, const float* __restrict__ x1,
              const float* __restrict__ x2, const float* __restrict__ x3,
              const float* __restrict__ x4,
              const float* __restrict__ f0, const float* __restrict__ f1,
              const float* __restrict__ f2, const float* __restrict__ f3,
              const float* __restrict__ f4,
              float* __restrict__ out) {
    extern __shared__ char smem[];
    __half* AH = (__half*)smem;             // 128 x PITCH
    __half* BH = AH + 128 * PITCH;          // 128 x PITCH
    float*  T  = (float*)smem;              // epilogue overlay (128 x FPITCH)

    // ---- level / tile decode (n-tiles of 128) ----
    const int bx = blockIdx.x;
    int L, t0;
    if (bx < 4096)      { L = 0; t0 = bx; }
    else if (bx < 5120) { L = 1; t0 = bx - 4096; }
    else if (bx < 5376) { L = 2; t0 = bx - 5120; }
    else if (bx < 5440) { L = 3; t0 = bx - 5376; }
    else                { L = 4; t0 = bx - 5440; }

    int N, nT;
    long long yoff;
    const float *X, *F;
    if (L == 0)      { N = 16384; nT = 128; yoff = 0LL;        X = x0; F = f0; }
    else if (L == 1) { N = 4096;  nT = 32;  yoff = 67108864LL; X = x1; F = f1; }
    else if (L == 2) { N = 1024;  nT = 8;   yoff = 83886080LL; X = x2; F = f2; }
    else if (L == 3) { N = 256;   nT = 2;   yoff = 88080384LL; X = x3; F = f3; }
    else             { N = 64;    nT = 1;   yoff = 89128960LL; X = x4; F = f4; }

    const int b    = t0 / nT;
    const int tile = t0 - b * nT;
    const int n0   = tile * 128;

    X += (size_t)b * 128 * N;
    F += (size_t)b * 128 * 128;
    float* Y = out + yoff + (size_t)b * 128 * N;

    const int tid = threadIdx.x;

    // ---- load F -> AH (coalesced float4; 16 float4 per thread) ----
#pragma unroll
    for (int i = 0; i < 16; i++) {
        const int e   = (i * 256 + tid) * 4;
        const int row = e >> 7;
        const int k   = e & 127;
        const float4 f = *(const float4*)(F + e);
        uint2 hi2;
        hi2.x = pack_h2(f.x, f.y);
        hi2.y = pack_h2(f.z, f.w);
        *(uint2*)(AH + row * PITCH + k) = hi2;
    }

    // ---- load X^T tile -> BH (coalesced LDG.32; B[n][k] = X[k][n0+n]) ----
    {
        const int n  = tid & 127;          // 128 threads -> 512B coalesced
        const int c0 = (tid >> 7) * 64;    // two K halves
        const bool nv = (n0 + n) < N;      // level-4 tail rows
        const float* xp = X + (size_t)c0 * N + n0 + n;
#pragma unroll
        for (int c = 0; c < 64; c += 2) {
            float v0 = 0.f, v1 = 0.f;
            if (nv) {
                v0 = xp[(size_t)c * N];
                v1 = xp[(size_t)(c + 1) * N];
            }
            *(uint32_t*)(BH + n * PITCH + c0 + c) = pack_h2(v0, v1);
        }
    }
    __syncthreads();

    // ---- HMMA mainloop: warp tile 32m x 64n, 8 k-steps ----
    const int wid  = tid >> 5;
    const int lane = tid & 31;
    const int wm   = (wid >> 1) * 32;
    const int wn   = (wid & 1) * 64;

    float d[16][4];
#pragma unroll
    for (int i = 0; i < 16; i++)
#pragma unroll
        for (int j = 0; j < 4; j++) d[i][j] = 0.f;

    const int arow = lane & 15;
    const int acol = (lane >> 4) * 8;
    const int brow = (lane & 7) + ((lane >> 4) << 3);
    const int bcol = ((lane >> 3) & 1) * 8;

    const uint32_t aB0 = smem_u32(AH + (wm + arow) * PITCH + acol);
    const uint32_t aB1 = aB0 + 16 * PITCH * 2;
    const uint32_t bB  = smem_u32(BH + (wn + brow) * PITCH + bcol);

#pragma unroll
    for (int ks = 0; ks < 8; ks++) {
        const uint32_t ko = ks * 32;  // 16 halves = 32 B
        uint32_t bb[4][4];
#pragma unroll
        for (int t = 0; t < 4; t++)
            LDSM4(bb[t], bB + t * (16 * PITCH * 2) + ko);

        uint32_t a0[4], a1[4];
        LDSM4(a0, aB0 + ko);
        LDSM4(a1, aB1 + ko);
#pragma unroll
        for (int t = 0; t < 4; t++) {
            MMA16816(d[2 * t + 0], a0, bb[t][0], bb[t][1]);
            MMA16816(d[2 * t + 1], a0, bb[t][2], bb[t][3]);
            MMA16816(d[2 * t + 8], a1, bb[t][0], bb[t][1]);
            MMA16816(d[2 * t + 9], a1, bb[t][2], bb[t][3]);
        }
    }
    __syncthreads();   // all warps done reading AH/BH before T overlays them

    // ---- epilogue: d frags -> smem bounce -> coalesced STG ----
#pragma unroll
    for (int mi = 0; mi < 2; mi++)
#pragma unroll
        for (int nj = 0; nj < 8; nj++) {
            const int row = wm + mi * 16 + (lane >> 2);
            const int col = wn + nj * 8 + 2 * (lane & 3);
            const float* dd = d[mi * 8 + nj];
            *(float2*)&T[row * FPITCH + col]       = make_float2(dd[0], dd[1]);
            *(float2*)&T[(row + 8) * FPITCH + col] = make_float2(dd[2], dd[3]);
        }
    __syncthreads();

    const int r0 = tid >> 5;            // 0..7
    const int c0 = (tid & 31) * 4;      // 0..124
    const bool sv = (L < 4) || (c0 < 64);   // level-4 tail columns (n0 == 0 there)
#pragma unroll
    for (int i = 0; i < 16; i++) {
        const int row = r0 + i * 8;
        const float4 v = *(const float4*)&T[row * FPITCH + c0];
        if (sv) *(float4*)&Y[(size_t)row * N + n0 + c0] = v;
    }
}

// ---------------- kernel 2: register-resident instance norm ----------------
template <int ITERS>
__global__ __launch_bounds__(256)
void lg5_norm_k(float* __restrict__ out, size_t yoff, int N) {
    float* row = out + yoff + (size_t)blockIdx.x * N;
    const int tid = threadIdx.x;

    float4 v[ITERS];
    float s1 = 0.f, s2 = 0.f;
#pragma unroll
    for (int i = 0; i < ITERS; i++) {
        const int idx = i * 1024 + tid * 4;
        if (idx < N) {
            v[i] = *(const float4*)(row + idx);
            s1 += v[i].x + v[i].y + v[i].z + v[i].w;
            s2 += v[i].x * v[i].x + v[i].y * v[i].y + v[i].z * v[i].z + v[i].w * v[i].w;
        }
    }
#pragma unroll
    for (int dl = 16; dl >= 1; dl >>= 1) {
        s1 += __shfl_xor_sync(0xffffffffu, s1, dl);
        s2 += __shfl_xor_sync(0xffffffffu, s2, dl);
    }
    __shared__ float a1[8], a2[8], st[2];
    const int w = tid >> 5, lane = tid & 31;
    if (lane == 0) { a1[w] = s1; a2[w] = s2; }
    __syncthreads();
    if (tid == 0) {
        float S1 = 0.f, S2 = 0.f;
#pragma unroll
        for (int i = 0; i < 8; i++) { S1 += a1[i]; S2 += a2[i]; }
        const float invN = 1.0f / (float)N;
        const float mean = S1 * invN;
        const float var  = S2 * invN - mean * mean;
        st[0] = mean;
        st[1] = rsqrtf(var + EPSN);
    }
    __syncthreads();
    const float mean = st[0], rstd = st[1];
#pragma unroll
    for (int i = 0; i < ITERS; i++) {
        const int idx = i * 1024 + tid * 4;
        if (idx < N) {
            float4 t = v[i];
            t.x = (t.x - mean) * rstd;
            t.y = (t.y - mean) * rstd;
            t.z = (t.z - mean) * rstd;
            t.w = (t.w - mean) * rstd;
            *(float4*)(row + idx) = t;
        }
    }
}

// merged norm for levels 1-3 (N = 4096 / 1024 / 256 via blockIdx.y)
__global__ __launch_bounds__(256)
void lg5_norm_small(float* __restrict__ out) {
    int N;
    size_t yoff;
    if (blockIdx.y == 0)      { N = 4096; yoff = 67108864ULL; }
    else if (blockIdx.y == 1) { N = 1024; yoff = 83886080ULL; }
    else                      { N = 256;  yoff = 88080384ULL; }

    float* row = out + yoff + (size_t)blockIdx.x * N;
    const int tid = threadIdx.x;

    float4 v[4];
    float s1 = 0.f, s2 = 0.f;
#pragma unroll
    for (int i = 0; i < 4; i++) {
        const int idx = i * 1024 + tid * 4;
        if (idx < N) {
            v[i] = *(const float4*)(row + idx);
            s1 += v[i].x + v[i].y + v[i].z + v[i].w;
            s2 += v[i].x * v[i].x + v[i].y * v[i].y + v[i].z * v[i].z + v[i].w * v[i].w;
        }
    }
#pragma unroll
    for (int dl = 16; dl >= 1; dl >>= 1) {
        s1 += __shfl_xor_sync(0xffffffffu, s1, dl);
        s2 += __shfl_xor_sync(0xffffffffu, s2, dl);
    }
    __shared__ float a1[8], a2[8], st[2];
    const int w = tid >> 5, lane = tid & 31;
    if (lane == 0) { a1[w] = s1; a2[w] = s2; }
    __syncthreads();
    if (tid == 0) {
        float S1 = 0.f, S2 = 0.f;
#pragma unroll
        for (int i = 0; i < 8; i++) { S1 += a1[i]; S2 += a2[i]; }
        const float invN = 1.0f / (float)N;
        const float mean = S1 * invN;
        const float var  = S2 * invN - mean * mean;
        st[0] = mean;
        st[1] = rsqrtf(var + EPSN);
    }
    __syncthreads();
    const float mean = st[0], rstd = st[1];
#pragma unroll
    for (int i = 0; i < 4; i++) {
        const int idx = i * 1024 + tid * 4;
        if (idx < N) {
            float4 t = v[i];
            t.x = (t.x - mean) * rstd;
            t.y = (t.y - mean) * rstd;
            t.z = (t.z - mean) * rstd;
            t.w = (t.w - mean) * rstd;
            *(float4*)(row + idx) = t;
        }
    }
}

// ---------------- launch ----------------
extern "C" void kernel_launch(void* const* d_in, const int* in_sizes, int n_in,
                              void* d_out, int out_size) {
    const float* xs[5] = {0, 0, 0, 0, 0};
    const float* fs[5] = {0, 0, 0, 0, 0};
    int fc = 0;
    for (int i = 0; i < n_in; i++) {
        const float* p = (const float*)d_in[i];
        switch (in_sizes[i]) {
            case 67108864: xs[0] = p; break;
            case 16777216: xs[1] = p; break;
            case 4194304:  xs[2] = p; break;
            case 1048576:  xs[3] = p; break;
            case 262144:   xs[4] = p; break;
            case 524288:   if (fc < 5) fs[fc++] = p; break;
        }
    }
    float* out = (float*)d_out;

    const int smem_bytes = 2 * 128 * PITCH * 2;   // AH + BH = 69632 B
    cudaFuncSetAttribute(lg5_hmma, cudaFuncAttributeMaxDynamicSharedMemorySize, smem_bytes);
    lg5_hmma<<<5472, 256, smem_bytes>>>(xs[0], xs[1], xs[2], xs[3], xs[4],
                                        fs[0], fs[1], fs[2], fs[3], fs[4], out);

    lg5_norm_k<16><<<4096, 256>>>(out, 0, 16384);
    lg5_norm_small<<<dim3(4096, 3), 256>>>(out);
}

// round 8
// speedup vs baseline: 1.9059x; 1.9059x over previous
#include <cuda_runtime.h>
#include <cuda_fp16.h>
#include <cstdint>

// Lingunet5Filter — HMMA fp16 single-product GEMM:
//   D = fp16(F) * fp16(X), fp32 accum.  Aggregate rel err ~3e-4 (threshold 1e-3).
//   Y[b](128 x N) = F[b](128x128) @ X[b](128 x N), N in {16384,4096,1024,256,64}, B=32
// + register-resident instance-norm kernels (levels 0-3).
//
// R8: launch_bounds (256,2) — (256,3) capped regs at 80 and spilled the 64-float
// accumulator array to local memory (R7 regression).

#define EPSN  1e-5f
#define PITCH 136   // fp16 elems per smem row (272 B) -> ldmatrix conflict-free
#define FPITCH 132  // float elems per epilogue bounce row

static __device__ __forceinline__ uint32_t smem_u32(const void* p) {
    uint32_t a;
    asm("{ .reg .u64 t; cvta.to.shared.u64 t, %1; cvt.u32.u64 %0, t; }" : "=r"(a) : "l"(p));
    return a;
}
static __device__ __forceinline__ uint32_t pack_h2(float a, float b) {
    __half2 t = __floats2half2_rn(a, b);
    return *reinterpret_cast<uint32_t*>(&t);
}

#define LDSM4(r, addr)                                                          \
    asm volatile("ldmatrix.sync.aligned.m8n8.x4.shared.b16 {%0,%1,%2,%3}, [%4];" \
                 : "=r"((r)[0]), "=r"((r)[1]), "=r"((r)[2]), "=r"((r)[3])        \
                 : "r"(addr))

#define MMA16816(d, a, b0, b1)                                                  \
    asm volatile("mma.sync.aligned.m16n8k16.row.col.f32.f16.f16.f32 "            \
                 "{%0,%1,%2,%3}, {%4,%5,%6,%7}, {%8,%9}, {%0,%1,%2,%3};"         \
                 : "+f"((d)[0]), "+f"((d)[1]), "+f"((d)[2]), "+f"((d)[3])        \
                 : "r"((a)[0]), "r"((a)[1]), "r"((a)[2]), "r"((a)[3]),           \
                   "r"(b0), "r"(b1))

// ---------------- kernel 1: HMMA batched GEMM (CTA tile 128m x 128n, K=128) ----------------
__global__ __launch_bounds__(256, 2)
void lg5_hmma(const float* __restrict__ x0, const float* __restrict__ x1,
              const float* __restrict__ x2, const float* __restrict__ x3,
              const float* __restrict__ x4,
              const float* __restrict__ f0, const float* __restrict__ f1,
              const float* __restrict__ f2, const float* __restrict__ f3,
              const float* __restrict__ f4,
              float* __restrict__ out) {
    extern __shared__ char smem[];
    __half* AH = (__half*)smem;             // 128 x PITCH
    __half* BH = AH + 128 * PITCH;          // 128 x PITCH
    float*  T  = (float*)smem;              // epilogue overlay (128 x FPITCH)

    // ---- level / tile decode (n-tiles of 128) ----
    const int bx = blockIdx.x;
    int L, t0;
    if (bx < 4096)      { L = 0; t0 = bx; }
    else if (bx < 5120) { L = 1; t0 = bx - 4096; }
    else if (bx < 5376) { L = 2; t0 = bx - 5120; }
    else if (bx < 5440) { L = 3; t0 = bx - 5376; }
    else                { L = 4; t0 = bx - 5440; }

    int N, nT;
    long long yoff;
    const float *X, *F;
    if (L == 0)      { N = 16384; nT = 128; yoff = 0LL;        X = x0; F = f0; }
    else if (L == 1) { N = 4096;  nT = 32;  yoff = 67108864LL; X = x1; F = f1; }
    else if (L == 2) { N = 1024;  nT = 8;   yoff = 83886080LL; X = x2; F = f2; }
    else if (L == 3) { N = 256;   nT = 2;   yoff = 88080384LL; X = x3; F = f3; }
    else             { N = 64;    nT = 1;   yoff = 89128960LL; X = x4; F = f4; }

    const int b    = t0 / nT;
    const int tile = t0 - b * nT;
    const int n0   = tile * 128;

    X += (size_t)b * 128 * N;
    F += (size_t)b * 128 * 128;
    float* Y = out + yoff + (size_t)b * 128 * N;

    const int tid = threadIdx.x;

    // ---- load F -> AH (coalesced float4; 16 float4 per thread) ----
#pragma unroll
    for (int i = 0; i < 16; i++) {
        const int e   = (i * 256 + tid) * 4;
        const int row = e >> 7;
        const int k   = e & 127;
        const float4 f = *(const float4*)(F + e);
        uint2 hi2;
        hi2.x = pack_h2(f.x, f.y);
        hi2.y = pack_h2(f.z, f.w);
        *(uint2*)(AH + row * PITCH + k) = hi2;
    }

    // ---- load X^T tile -> BH (coalesced LDG.32; B[n][k] = X[k][n0+n]) ----
    {
        const int n  = tid & 127;          // 128 threads -> 512B coalesced
        const int c0 = (tid >> 7) * 64;    // two K halves
        const bool nv = (n0 + n) < N;      // level-4 tail rows
        const float* xp = X + (size_t)c0 * N + n0 + n;
#pragma unroll
        for (int c = 0; c < 64; c += 2) {
            float v0 = 0.f, v1 = 0.f;
            if (nv) {
                v0 = xp[(size_t)c * N];
                v1 = xp[(size_t)(c + 1) * N];
            }
            *(uint32_t*)(BH + n * PITCH + c0 + c) = pack_h2(v0, v1);
        }
    }
    __syncthreads();

    // ---- HMMA mainloop: warp tile 32m x 64n, 8 k-steps ----
    const int wid  = tid >> 5;
    const int lane = tid & 31;
    const int wm   = (wid >> 1) * 32;
    const int wn   = (wid & 1) * 64;

    float d[16][4];
#pragma unroll
    for (int i = 0; i < 16; i++)
#pragma unroll
        for (int j = 0; j < 4; j++) d[i][j] = 0.f;

    const int arow = lane & 15;
    const int acol = (lane >> 4) * 8;
    const int brow = (lane & 7) + ((lane >> 4) << 3);
    const int bcol = ((lane >> 3) & 1) * 8;

    const uint32_t aB0 = smem_u32(AH + (wm + arow) * PITCH + acol);
    const uint32_t aB1 = aB0 + 16 * PITCH * 2;
    const uint32_t bB  = smem_u32(BH + (wn + brow) * PITCH + bcol);

#pragma unroll
    for (int ks = 0; ks < 8; ks++) {
        const uint32_t ko = ks * 32;  // 16 halves = 32 B
        uint32_t bb[4][4];
#pragma unroll
        for (int t = 0; t < 4; t++)
            LDSM4(bb[t], bB + t * (16 * PITCH * 2) + ko);

        uint32_t a0[4], a1[4];
        LDSM4(a0, aB0 + ko);
        LDSM4(a1, aB1 + ko);
#pragma unroll
        for (int t = 0; t < 4; t++) {
            MMA16816(d[2 * t + 0], a0, bb[t][0], bb[t][1]);
            MMA16816(d[2 * t + 1], a0, bb[t][2], bb[t][3]);
            MMA16816(d[2 * t + 8], a1, bb[t][0], bb[t][1]);
            MMA16816(d[2 * t + 9], a1, bb[t][2], bb[t][3]);
        }
    }
    __syncthreads();   // all warps done reading AH/BH before T overlays them

    // ---- epilogue: d frags -> smem bounce -> coalesced STG ----
#pragma unroll
    for (int mi = 0; mi < 2; mi++)
#pragma unroll
        for (int nj = 0; nj < 8; nj++) {
            const int row = wm + mi * 16 + (lane >> 2);
            const int col = wn + nj * 8 + 2 * (lane & 3);
            const float* dd = d[mi * 8 + nj];
            *(float2*)&T[row * FPITCH + col]       = make_float2(dd[0], dd[1]);
            *(float2*)&T[(row + 8) * FPITCH + col] = make_float2(dd[2], dd[3]);
        }
    __syncthreads();

    const int r0 = tid >> 5;            // 0..7
    const int c0 = (tid & 31) * 4;      // 0..124
    const bool sv = (L < 4) || (c0 < 64);   // level-4 tail columns (n0 == 0 there)
#pragma unroll
    for (int i = 0; i < 16; i++) {
        const int row = r0 + i * 8;
        const float4 v = *(const float4*)&T[row * FPITCH + c0];
        if (sv) *(float4*)&Y[(size_t)row * N + n0 + c0] = v;
    }
}

// ---------------- kernel 2: register-resident instance norm ----------------
template <int ITERS>
__global__ __launch_bounds__(256)
void lg5_norm_k(float* __restrict__ out, size_t yoff, int N) {
    float* row = out + yoff + (size_t)blockIdx.x * N;
    const int tid = threadIdx.x;

    float4 v[ITERS];
    float s1 = 0.f, s2 = 0.f;
#pragma unroll
    for (int i = 0; i < ITERS; i++) {
        const int idx = i * 1024 + tid * 4;
        if (idx < N) {
            v[i] = *(const float4*)(row + idx);
            s1 += v[i].x + v[i].y + v[i].z + v[i].w;
            s2 += v[i].x * v[i].x + v[i].y * v[i].y + v[i].z * v[i].z + v[i].w * v[i].w;
        }
    }
#pragma unroll
    for (int dl = 16; dl >= 1; dl >>= 1) {
        s1 += __shfl_xor_sync(0xffffffffu, s1, dl);
        s2 += __shfl_xor_sync(0xffffffffu, s2, dl);
    }
    __shared__ float a1[8], a2[8], st[2];
    const int w = tid >> 5, lane = tid & 31;
    if (lane == 0) { a1[w] = s1; a2[w] = s2; }
    __syncthreads();
    if (tid == 0) {
        float S1 = 0.f, S2 = 0.f;
#pragma unroll
        for (int i = 0; i < 8; i++) { S1 += a1[i]; S2 += a2[i]; }
        const float invN = 1.0f / (float)N;
        const float mean = S1 * invN;
        const float var  = S2 * invN - mean * mean;
        st[0] = mean;
        st[1] = rsqrtf(var + EPSN);
    }
    __syncthreads();
    const float mean = st[0], rstd = st[1];
#pragma unroll
    for (int i = 0; i < ITERS; i++) {
        const int idx = i * 1024 + tid * 4;
        if (idx < N) {
            float4 t = v[i];
            t.x = (t.x - mean) * rstd;
            t.y = (t.y - mean) * rstd;
            t.z = (t.z - mean) * rstd;
            t.w = (t.w - mean) * rstd;
            *(float4*)(row + idx) = t;
        }
    }
}

// merged norm for levels 1-3 (N = 4096 / 1024 / 256 via blockIdx.y)
__global__ __launch_bounds__(256)
void lg5_norm_small(float* __restrict__ out) {
    int N;
    size_t yoff;
    if (blockIdx.y == 0)      { N = 4096; yoff = 67108864ULL; }
    else if (blockIdx.y == 1) { N = 1024; yoff = 83886080ULL; }
    else                      { N = 256;  yoff = 88080384ULL; }

    float* row = out + yoff + (size_t)blockIdx.x * N;
    const int tid = threadIdx.x;

    float4 v[4];
    float s1 = 0.f, s2 = 0.f;
#pragma unroll
    for (int i = 0; i < 4; i++) {
        const int idx = i * 1024 + tid * 4;
        if (idx < N) {
            v[i] = *(const float4*)(row + idx);
            s1 += v[i].x + v[i].y + v[i].z + v[i].w;
            s2 += v[i].x * v[i].x + v[i].y * v[i].y + v[i].z * v[i].z + v[i].w * v[i].w;
        }
    }
#pragma unroll
    for (int dl = 16; dl >= 1; dl >>= 1) {
        s1 += __shfl_xor_sync(0xffffffffu, s1, dl);
        s2 += __shfl_xor_sync(0xffffffffu, s2, dl);
    }
    __shared__ float a1[8], a2[8], st[2];
    const int w = tid >> 5, lane = tid & 31;
    if (lane == 0) { a1[w] = s1; a2[w] = s2; }
    __syncthreads();
    if (tid == 0) {
        float S1 = 0.f, S2 = 0.f;
#pragma unroll
        for (int i = 0; i < 8; i++) { S1 += a1[i]; S2 += a2[i]; }
        const float invN = 1.0f / (float)N;
        const float mean = S1 * invN;
        const float var  = S2 * invN - mean * mean;
        st[0] = mean;
        st[1] = rsqrtf(var + EPSN);
    }
    __syncthreads();
    const float mean = st[0], rstd = st[1];
#pragma unroll
    for (int i = 0; i < 4; i++) {
        const int idx = i * 1024 + tid * 4;
        if (idx < N) {
            float4 t = v[i];
            t.x = (t.x - mean) * rstd;
            t.y = (t.y - mean) * rstd;
            t.z = (t.z - mean) * rstd;
            t.w = (t.w - mean) * rstd;
            *(float4*)(row + idx) = t;
        }
    }
}

// ---------------- launch ----------------
extern "C" void kernel_launch(void* const* d_in, const int* in_sizes, int n_in,
                              void* d_out, int out_size) {
    const float* xs[5] = {0, 0, 0, 0, 0};
    const float* fs[5] = {0, 0, 0, 0, 0};
    int fc = 0;
    for (int i = 0; i < n_in; i++) {
        const float* p = (const float*)d_in[i];
        switch (in_sizes[i]) {
            case 67108864: xs[0] = p; break;
            case 16777216: xs[1] = p; break;
            case 4194304:  xs[2] = p; break;
            case 1048576:  xs[3] = p; break;
            case 262144:   xs[4] = p; break;
            case 524288:   if (fc < 5) fs[fc++] = p; break;
        }
    }
    float* out = (float*)d_out;

    const int smem_bytes = 2 * 128 * PITCH * 2;   // AH + BH = 69632 B
    cudaFuncSetAttribute(lg5_hmma, cudaFuncAttributeMaxDynamicSharedMemorySize, smem_bytes);
    lg5_hmma<<<5472, 256, smem_bytes>>>(xs[0], xs[1], xs[2], xs[3], xs[4],
                                        fs[0], fs[1], fs[2], fs[3], fs[4], out);

    lg5_norm_k<16><<<4096, 256>>>(out, 0, 16384);
    lg5_norm_small<<<dim3(4096, 3), 256>>>(out);
}